// round 1
// baseline (speedup 1.0000x reference)
#include <cuda_runtime.h>
#include <cstdint>

// Problem shape (fixed by the dataset): (32, 1024, 2048) fp32
//   noisy = data + 0.1*noise
//   per row of D=2048: mask the K=512 positions holding the largest uniforms
//   (ties at the threshold broken by LOWEST index, matching jax.lax.top_k)
//   out[0:N)   = masked  (0 where masked, noisy elsewhere)
//   out[N:2N)  = mask_inverse (0 where masked, 1 elsewhere)

#define D_DIM 2048
#define K_SEL 512
#define TPB   256
#define EPT   8   // contiguous elements per thread (D_DIM / TPB)

__global__ __launch_bounds__(TPB)
void obs_mask_kernel(const float* __restrict__ data,
                     const float* __restrict__ noise,
                     const float* __restrict__ rand_vals,
                     float* __restrict__ out_masked,
                     float* __restrict__ out_inv)
{
    __shared__ unsigned s_hist[256];
    __shared__ unsigned s_warp[8];
    __shared__ unsigned s_bcast[2];   // [0] = selected bin, [1] = count strictly above bin

    const int tid  = threadIdx.x;
    const int lane = tid & 31;
    const int wid  = tid >> 5;
    const size_t base = (size_t)blockIdx.x * D_DIM;

    // ---- load this thread's contiguous 8 rand values as raw bits ----
    unsigned r[EPT];
    {
        const uint4* p = reinterpret_cast<const uint4*>(rand_vals + base) + (tid << 1);
        uint4 a = p[0], b = p[1];
        r[0] = a.x; r[1] = a.y; r[2] = a.z; r[3] = a.w;
        r[4] = b.x; r[5] = b.y; r[6] = b.z; r[7] = b.w;
    }

    // ---- 4-pass byte radix select: find K_SEL-th largest bit pattern ----
    // All values are non-negative floats -> unsigned bit compare == float compare.
    unsigned prefix = 0;        // selected high bits so far
    unsigned rem    = K_SEL;    // rank remaining within current prefix group

    #pragma unroll
    for (int pass = 0; pass < 4; ++pass) {
        const int shift = 24 - 8 * pass;
        const unsigned pmask = (pass == 0) ? 0u : (0xFFFFFFFFu << (shift + 8));

        s_hist[tid] = 0;
        __syncthreads();

        #pragma unroll
        for (int j = 0; j < EPT; ++j) {
            bool pred = ((r[j] & pmask) == prefix);
            unsigned active = __ballot_sync(0xFFFFFFFFu, pred);
            if (pred) {
                unsigned bin   = (r[j] >> shift) & 255u;
                unsigned peers = __match_any_sync(active, bin);
                int leader     = __ffs(peers) - 1;
                if (lane == leader) atomicAdd(&s_hist[bin], (unsigned)__popc(peers));
            }
        }
        __syncthreads();

        // suffix (descending-cumulative) sum over the 256 bins, shuffle-based
        unsigned h = s_hist[tid];
        unsigned v = h;
        #pragma unroll
        for (int off = 1; off < 32; off <<= 1) {
            unsigned o = __shfl_down_sync(0xFFFFFFFFu, v, off);
            if (lane + off < 32) v += o;
        }
        if (lane == 0) s_warp[wid] = v;   // warp total (lane 0 holds full-warp suffix)
        __syncthreads();
        unsigned addHi = 0;
        #pragma unroll
        for (int w = 0; w < 8; ++w)
            if (w > wid) addHi += s_warp[w];
        unsigned S     = v + addHi;   // sum of hist[t..255]
        unsigned Snext = S - h;       // sum of hist[t+1..255]
        if (S >= rem && Snext < rem) {   // unique bin: S decreasing in t
            s_bcast[0] = (unsigned)tid;
            s_bcast[1] = Snext;
        }
        __syncthreads();
        prefix |= s_bcast[0] << shift;
        rem    -= s_bcast[1];
        // (next pass zeroes s_hist and syncs before any shared reuse)
    }

    const unsigned T = prefix;   // threshold bit pattern (the K-th largest value)
    const unsigned m = rem;      // how many threshold-equal elements to mask (lowest index first)

    // ---- exclusive block scan of per-thread equal-to-T counts (index order) ----
    unsigned cnt = 0;
    #pragma unroll
    for (int j = 0; j < EPT; ++j) cnt += (r[j] == T) ? 1u : 0u;

    unsigned iv = cnt;
    #pragma unroll
    for (int off = 1; off < 32; off <<= 1) {
        unsigned o = __shfl_up_sync(0xFFFFFFFFu, iv, off);
        if (lane >= off) iv += o;
    }
    if (lane == 31) s_warp[wid] = iv;   // safe: all pass-4 s_warp reads are behind the last sync
    __syncthreads();
    unsigned wOff = 0;
    #pragma unroll
    for (int w = 0; w < 8; ++w)
        if (w < wid) wOff += s_warp[w];
    unsigned eqRank = wOff + iv - cnt;  // exclusive prefix: equals with smaller index

    // ---- fused noise + mask + dual output, contiguous float4 I/O ----
    const float4* dp = reinterpret_cast<const float4*>(data  + base) + (tid << 1);
    const float4* np = reinterpret_cast<const float4*>(noise + base) + (tid << 1);
    float4* mp = reinterpret_cast<float4*>(out_masked + base) + (tid << 1);
    float4* ip = reinterpret_cast<float4*>(out_inv    + base) + (tid << 1);

    #pragma unroll
    for (int h4 = 0; h4 < 2; ++h4) {
        float4 d4 = dp[h4];
        float4 n4 = np[h4];
        float dv[4] = {d4.x, d4.y, d4.z, d4.w};
        float nv[4] = {n4.x, n4.y, n4.z, n4.w};
        float ov[4], gv[4];
        #pragma unroll
        for (int c = 0; c < 4; ++c) {
            int j = h4 * 4 + c;
            bool masked;
            if (r[j] > T) {
                masked = true;
            } else if (r[j] == T) {
                masked = (eqRank < m);
                eqRank++;
            } else {
                masked = false;
            }
            ov[c] = masked ? 0.0f : fmaf(0.1f, nv[c], dv[c]);
            gv[c] = masked ? 0.0f : 1.0f;
        }
        mp[h4] = make_float4(ov[0], ov[1], ov[2], ov[3]);
        ip[h4] = make_float4(gv[0], gv[1], gv[2], gv[3]);
    }
}

extern "C" void kernel_launch(void* const* d_in, const int* in_sizes, int n_in,
                              void* d_out, int out_size)
{
    const float* data  = (const float*)d_in[0];
    const float* noise = (const float*)d_in[1];
    const float* rv    = (const float*)d_in[2];
    float* out = (float*)d_out;

    size_t n = (size_t)in_sizes[0];            // 32*1024*2048 elements
    int rows = (int)(n / D_DIM);               // 32768 rows

    obs_mask_kernel<<<rows, TPB>>>(data, noise, rv, out, out + n);
}

// round 2
// speedup vs baseline: 1.2834x; 1.2834x over previous
#include <cuda_runtime.h>
#include <cstdint>

// (32, 1024, 2048) fp32.  noisy = data + 0.1*noise; mask top-512 uniforms per row
// (ties at threshold -> lowest index first, matching jax.lax.top_k stability).
// out[0:N) = masked, out[N:2N) = mask_inverse.

#define D_DIM    2048
#define K_SEL    512
#define TPB      256
#define EPT      8          // D_DIM / TPB, contiguous per thread
#define NBINS    2048
#define BIN_BASE 0x3780u    // top16 of ~2^-33; uniform top-512 threshold is vastly above this

__global__ __launch_bounds__(TPB)
void obs_mask_kernel(const float* __restrict__ data,
                     const float* __restrict__ noise,
                     const float* __restrict__ rand_vals,
                     float* __restrict__ out_masked,
                     float* __restrict__ out_inv)
{
    __shared__ unsigned s_hist[NBINS];   // stage 1: 2048 bins; byte passes reuse first 256
    __shared__ unsigned s_warp[8];
    __shared__ unsigned s_bcast[2];      // [0]=selected bin, [1]=count strictly above bin

    const int tid  = threadIdx.x;
    const int lane = tid & 31;
    const int wid  = tid >> 5;
    const size_t base = (size_t)blockIdx.x * D_DIM;

    // ---- load 8 contiguous rand values as raw bits (non-negative floats: uint cmp == float cmp)
    unsigned r[EPT];
    {
        const uint4* p = reinterpret_cast<const uint4*>(rand_vals + base) + (tid << 1);
        uint4 a = p[0], b = p[1];
        r[0] = a.x; r[1] = a.y; r[2] = a.z; r[3] = a.w;
        r[4] = b.x; r[5] = b.y; r[6] = b.z; r[7] = b.w;
    }

    // ---- zero 2048-bin histogram (vectorized) ----
    {
        uint4* hz = reinterpret_cast<uint4*>(s_hist);
        uint4 z = make_uint4(0, 0, 0, 0);
        hz[tid]       = z;
        hz[tid + 256] = z;
    }
    __syncthreads();

    // ---- STAGE 1: 16-bit histogram, plain shared atomics (≈1 hit/bin => no contention) ----
    #pragma unroll
    for (int j = 0; j < EPT; ++j) {
        unsigned t16 = r[j] >> 16;
        unsigned bin = (t16 > BIN_BASE) ? (t16 - BIN_BASE) : 0u;
        atomicAdd(&s_hist[bin], 1u);
    }
    __syncthreads();

    unsigned rem = K_SEL;

    // ---- 2048-bin suffix scan + select (thread t owns bins [8t, 8t+8), LDS.128 loads) ----
    {
        const uint4* hz = reinterpret_cast<const uint4*>(s_hist);
        uint4 h0 = hz[tid * 2];
        uint4 h1 = hz[tid * 2 + 1];
        unsigned hloc[8] = {h0.x, h0.y, h0.z, h0.w, h1.x, h1.y, h1.z, h1.w};

        unsigned locsuf[8];
        unsigned acc = 0;
        #pragma unroll
        for (int j = 7; j >= 0; --j) { acc += hloc[j]; locsuf[j] = acc; }
        unsigned tot = acc;

        // warp-inclusive suffix over per-thread totals
        unsigned v = tot;
        #pragma unroll
        for (int off = 1; off < 32; off <<= 1) {
            unsigned o = __shfl_down_sync(0xFFFFFFFFu, v, off);
            if (lane + off < 32) v += o;
        }
        if (lane == 0) s_warp[wid] = v;
        __syncthreads();
        unsigned above = 0;
        #pragma unroll
        for (int w = 0; w < 8; ++w)
            if (w > wid) above += s_warp[w];
        unsigned sufAbove = above + (v - tot);   // strictly-above-this-thread suffix

        #pragma unroll
        for (int j = 0; j < 8; ++j) {
            unsigned S = sufAbove + locsuf[j];
            unsigned h = hloc[j];
            if (S >= rem && S - h < rem) {       // unique crossing bin (h > 0)
                s_bcast[0] = (unsigned)(tid * 8 + j);
                s_bcast[1] = S - h;
            }
        }
        __syncthreads();
    }

    unsigned binSel = s_bcast[0];
    unsigned T;

    if (binSel != 0u) {
        rem -= s_bcast[1];
        T = (binSel + BIN_BASE) << 16;
        __syncthreads();   // all bcast reads done before smem reuse

        // ---- STAGE 2: two byte-passes over ~8 candidates (plain atomics) ----
        #pragma unroll
        for (int pass = 0; pass < 2; ++pass) {
            const int shift = 8 - 8 * pass;                       // 8 then 0
            const unsigned pmask = (pass == 0) ? 0xFFFF0000u : 0xFFFFFF00u;

            s_hist[tid] = 0;
            __syncthreads();
            #pragma unroll
            for (int j = 0; j < EPT; ++j) {
                if ((r[j] & pmask) == T)
                    atomicAdd(&s_hist[(r[j] >> shift) & 255u], 1u);
            }
            __syncthreads();

            unsigned h = s_hist[tid];
            unsigned v = h;
            #pragma unroll
            for (int off = 1; off < 32; off <<= 1) {
                unsigned o = __shfl_down_sync(0xFFFFFFFFu, v, off);
                if (lane + off < 32) v += o;
            }
            if (lane == 0) s_warp[wid] = v;
            __syncthreads();
            unsigned addHi = 0;
            #pragma unroll
            for (int w = 0; w < 8; ++w)
                if (w > wid) addHi += s_warp[w];
            unsigned S = v + addHi;
            unsigned Snext = S - h;
            if (S >= rem && Snext < rem) {
                s_bcast[0] = (unsigned)tid;
                s_bcast[1] = Snext;
            }
            __syncthreads();
            T   |= s_bcast[0] << shift;
            rem -= s_bcast[1];
            __syncthreads();
        }
    } else {
        // ---- FALLBACK (statistically unreachable): generic 4-pass byte radix ----
        __syncthreads();
        unsigned prefix = 0;
        rem = K_SEL;
        for (int pass = 0; pass < 4; ++pass) {
            const int shift = 24 - 8 * pass;
            const unsigned pmask = (pass == 0) ? 0u : (0xFFFFFFFFu << (shift + 8));

            s_hist[tid] = 0;
            __syncthreads();
            for (int j = 0; j < EPT; ++j) {
                if ((r[j] & pmask) == prefix)
                    atomicAdd(&s_hist[(r[j] >> shift) & 255u], 1u);
            }
            __syncthreads();

            unsigned h = s_hist[tid];
            unsigned v = h;
            for (int off = 1; off < 32; off <<= 1) {
                unsigned o = __shfl_down_sync(0xFFFFFFFFu, v, off);
                if (lane + off < 32) v += o;
            }
            if (lane == 0) s_warp[wid] = v;
            __syncthreads();
            unsigned addHi = 0;
            for (int w = 0; w < 8; ++w)
                if (w > wid) addHi += s_warp[w];
            unsigned S = v + addHi;
            unsigned Snext = S - h;
            if (S >= rem && Snext < rem) {
                s_bcast[0] = (unsigned)tid;
                s_bcast[1] = Snext;
            }
            __syncthreads();
            prefix |= s_bcast[0] << shift;
            rem    -= s_bcast[1];
            __syncthreads();
        }
        T = prefix;
    }

    const unsigned m = rem;   // threshold-equal elements to mask (lowest indices first)

    // ---- exclusive block scan of per-thread equal-to-T counts (index order) ----
    unsigned cnt = 0;
    #pragma unroll
    for (int j = 0; j < EPT; ++j) cnt += (r[j] == T) ? 1u : 0u;

    unsigned iv = cnt;
    #pragma unroll
    for (int off = 1; off < 32; off <<= 1) {
        unsigned o = __shfl_up_sync(0xFFFFFFFFu, iv, off);
        if (lane >= off) iv += o;
    }
    if (lane == 31) s_warp[wid] = iv;
    __syncthreads();
    unsigned wOff = 0;
    #pragma unroll
    for (int w = 0; w < 8; ++w)
        if (w < wid) wOff += s_warp[w];
    unsigned eqRank = wOff + iv - cnt;

    // ---- fused noise + mask + dual output, float4 I/O ----
    const float4* dp = reinterpret_cast<const float4*>(data  + base) + (tid << 1);
    const float4* np = reinterpret_cast<const float4*>(noise + base) + (tid << 1);
    float4* mp = reinterpret_cast<float4*>(out_masked + base) + (tid << 1);
    float4* ip = reinterpret_cast<float4*>(out_inv    + base) + (tid << 1);

    #pragma unroll
    for (int h4 = 0; h4 < 2; ++h4) {
        float4 d4 = dp[h4];
        float4 n4 = np[h4];
        float dv[4] = {d4.x, d4.y, d4.z, d4.w};
        float nv[4] = {n4.x, n4.y, n4.z, n4.w};
        float ov[4], gv[4];
        #pragma unroll
        for (int c = 0; c < 4; ++c) {
            int j = h4 * 4 + c;
            bool masked;
            if (r[j] > T) {
                masked = true;
            } else if (r[j] == T) {
                masked = (eqRank < m);
                eqRank++;
            } else {
                masked = false;
            }
            ov[c] = masked ? 0.0f : fmaf(0.1f, nv[c], dv[c]);
            gv[c] = masked ? 0.0f : 1.0f;
        }
        mp[h4] = make_float4(ov[0], ov[1], ov[2], ov[3]);
        ip[h4] = make_float4(gv[0], gv[1], gv[2], gv[3]);
    }
}

extern "C" void kernel_launch(void* const* d_in, const int* in_sizes, int n_in,
                              void* d_out, int out_size)
{
    const float* data  = (const float*)d_in[0];
    const float* noise = (const float*)d_in[1];
    const float* rv    = (const float*)d_in[2];
    float* out = (float*)d_out;

    size_t n = (size_t)in_sizes[0];   // 32*1024*2048
    int rows = (int)(n / D_DIM);      // 32768

    obs_mask_kernel<<<rows, TPB>>>(data, noise, rv, out, out + n);
}

// round 3
// speedup vs baseline: 1.5818x; 1.2325x over previous
#include <cuda_runtime.h>
#include <cstdint>

// (32, 1024, 2048) fp32.  noisy = data + 0.1*noise; mask top-512 uniforms per row
// (ties at threshold -> lowest index first, matching jax.lax.top_k stability).
// out[0:N) = masked, out[N:2N) = mask_inverse.

#define D_DIM 2048
#define K_SEL 512
#define TPB   256
#define EPT   8          // D_DIM / TPB, contiguous per thread
#define FULLM 0xFFFFFFFFu

__global__ __launch_bounds__(TPB, 6)
void obs_mask_kernel(const float* __restrict__ data,
                     const float* __restrict__ noise,
                     const float* __restrict__ rand_vals,
                     float* __restrict__ out_masked,
                     float* __restrict__ out_inv)
{
    __shared__ unsigned s_hist[256];   // fast path uses [0..63]; fallback uses all 256
    __shared__ unsigned s_cnt[8];
    __shared__ unsigned s_cand[64];
    __shared__ unsigned s_bc[2];       // {selected t16 bin, count strictly above bin}
    __shared__ unsigned s_res[2];      // {T bits, idxT}
    __shared__ unsigned s_n;

    const int tid  = threadIdx.x;
    const int lane = tid & 31;
    const int wid  = tid >> 5;
    const size_t base = (size_t)blockIdx.x * D_DIM;
    const unsigned idxBase = (unsigned)tid << 3;

    // ---- load 8 contiguous rand values as raw bits (non-neg floats: uint cmp == float cmp)
    unsigned r[EPT];
    {
        const uint4* p = reinterpret_cast<const uint4*>(rand_vals + base) + (tid << 1);
        uint4 a = __ldcs(p);
        uint4 b = __ldcs(p + 1);
        r[0] = a.x; r[1] = a.y; r[2] = a.z; r[3] = a.w;
        r[4] = b.x; r[5] = b.y; r[6] = b.z; r[7] = b.w;
    }

    // ---- cheap exact band census: c1 = #{v>=0.75}, c2 = #{v>=0.5}, any >= 1.0 ----
    unsigned cpk = 0;   // c1 in low 16, c2 in high 16
    int big = 0;
    #pragma unroll
    for (int j = 0; j < EPT; ++j) {
        cpk += (r[j] >= 0x3F400000u) ? 1u : 0u;
        cpk += (r[j] >= 0x3F000000u) ? 0x10000u : 0u;
        big |= (r[j] >= 0x3F800000u);
    }
    #pragma unroll
    for (int off = 16; off >= 1; off >>= 1)
        cpk += __shfl_down_sync(FULLM, cpk, off);
    if (lane == 0) s_cnt[wid] = cpk;
    if (tid < 64) s_hist[tid] = 0;
    if (tid == 0) s_n = 0;

    int anyBig = __syncthreads_or(big);          // barrier #1

    unsigned csum = 0;
    #pragma unroll
    for (int w = 0; w < 8; ++w) csum += s_cnt[w];
    const unsigned c1 = csum & 0xFFFFu;
    const unsigned c2 = csum >> 16;

    bool generic = (anyBig != 0);
    unsigned lo16 = 0, remBand = 0;
    if (!generic) {
        if (c1 >= K_SEL)      { lo16 = 0x3F40u; remBand = K_SEL; }
        else if (c2 >= K_SEL) { lo16 = 0x3F00u; remBand = K_SEL - c1; }
        else                  { generic = true; }
    }

    if (!generic) {
        // ---- 64-bin histogram over the quarter-band only (~2 atomics/thread) ----
        #pragma unroll
        for (int j = 0; j < EPT; ++j) {
            unsigned bin = (r[j] >> 16) - lo16;
            if (bin < 64u) atomicAdd(&s_hist[bin], 1u);
        }
        __syncthreads();                         // barrier #2

        // ---- warp0: suffix scan of 64 bins, pick crossing bin ----
        if (wid == 0) {
            uint2 h2 = reinterpret_cast<const uint2*>(s_hist)[lane];  // bins 2l, 2l+1
            unsigned s1 = h2.y;
            unsigned s0 = h2.x + s1;
            unsigned inc = s0;
            #pragma unroll
            for (int off = 1; off < 32; off <<= 1) {
                unsigned o = __shfl_down_sync(FULLM, inc, off);
                if (lane + off < 32) inc += o;
            }
            unsigned abovePairs = inc - s0;
            unsigned S_hi = abovePairs + s1;      // bin 2l+1
            unsigned S_lo = abovePairs + s0;      // bin 2l
            if (S_hi >= remBand && S_hi - h2.y < remBand) {
                s_bc[0] = lo16 + 2u * lane + 1u;  s_bc[1] = S_hi - h2.y;
            }
            if (S_lo >= remBand && S_lo - h2.x < remBand) {
                s_bc[0] = lo16 + 2u * lane;       s_bc[1] = S_lo - h2.x;
            }
        }
        __syncthreads();                         // barrier #3

        const unsigned t16sel = s_bc[0];
        const unsigned rem2   = remBand - s_bc[1];   // rank within crossing bin, >= 1

        // ---- collect crossing-bin candidates as packed keys ----
        #pragma unroll
        for (int j = 0; j < EPT; ++j) {
            if ((r[j] >> 16) == t16sel) {
                unsigned key = ((r[j] & 0xFFFFu) << 11) | (2047u - (idxBase + j));
                unsigned pos = atomicAdd(&s_n, 1u);
                if (pos < 64u) s_cand[pos] = key;
            }
        }
        __syncthreads();                         // barrier #4

        unsigned n = s_n;
        if (n <= 64u) {
            // ---- warp0: exact rank-(rem2) select among n distinct keys ----
            if (wid == 0) {
                unsigned k0 = (lane < (int)n)        ? s_cand[lane]      : 0u;
                unsigned k1 = ((unsigned)lane + 32u < n) ? s_cand[lane + 32] : 0u;
                unsigned r0 = 0, r1 = 0;
                unsigned nn = n < 32u ? n : 32u;
                for (unsigned i = 0; i < nn; ++i) {
                    unsigned b = __shfl_sync(FULLM, k0, i);
                    r0 += (b > k0); r1 += (b > k1);
                }
                if (n > 32u) {
                    unsigned n2 = n - 32u;
                    for (unsigned i = 0; i < n2; ++i) {
                        unsigned b = __shfl_sync(FULLM, k1, i);
                        r0 += (b > k0); r1 += (b > k1);
                    }
                }
                unsigned target = rem2 - 1u;
                if ((unsigned)lane < n && r0 == target) {
                    s_res[0] = (t16sel << 16) | (k0 >> 11);
                    s_res[1] = 2047u - (k0 & 0x7FFu);
                }
                if ((unsigned)lane + 32u < n && r1 == target) {
                    s_res[0] = (t16sel << 16) | (k1 >> 11);
                    s_res[1] = 2047u - (k1 & 0x7FFu);
                }
            }
            __syncthreads();                     // barrier #5
        } else {
            generic = true;                      // block-uniform
        }
    }

    if (generic) {
        // ---- fully generic exact path: 4-pass byte radix + boundary index ----
        __syncthreads();
        unsigned prefix = 0, remG = K_SEL;
        for (int pass = 0; pass < 4; ++pass) {
            const int shift = 24 - 8 * pass;
            const unsigned pmask = (pass == 0) ? 0u : (0xFFFFFFFFu << (shift + 8));
            s_hist[tid] = 0;
            __syncthreads();
            for (int j = 0; j < EPT; ++j)
                if ((r[j] & pmask) == prefix)
                    atomicAdd(&s_hist[(r[j] >> shift) & 255u], 1u);
            __syncthreads();
            unsigned h = s_hist[tid], v = h;
            for (int off = 1; off < 32; off <<= 1) {
                unsigned o = __shfl_down_sync(FULLM, v, off);
                if (lane + off < 32) v += o;
            }
            if (lane == 0) s_cnt[wid] = v;
            __syncthreads();
            unsigned addHi = 0;
            for (int w = 0; w < 8; ++w)
                if (w > wid) addHi += s_cnt[w];
            unsigned S = v + addHi;
            if (S >= remG && S - h < remG) { s_bc[0] = (unsigned)tid; s_bc[1] = S - h; }
            __syncthreads();
            prefix |= s_bc[0] << shift;
            remG   -= s_bc[1];
            __syncthreads();
        }
        // locate idxT: index of the remG-th equal-to-prefix element (ascending index)
        unsigned cnt = 0;
        for (int j = 0; j < EPT; ++j) cnt += (r[j] == prefix) ? 1u : 0u;
        unsigned iv = cnt;
        for (int off = 1; off < 32; off <<= 1) {
            unsigned o = __shfl_up_sync(FULLM, iv, off);
            if (lane >= off) iv += o;
        }
        if (lane == 31) s_cnt[wid] = iv;
        __syncthreads();
        unsigned wOff = 0;
        for (int w = 0; w < 8; ++w)
            if (w < wid) wOff += s_cnt[w];
        unsigned excl = wOff + iv - cnt;
        if (excl < remG && remG <= excl + cnt) {
            unsigned need = remG - excl, run = 0;
            for (int j = 0; j < EPT; ++j)
                if (r[j] == prefix && ++run == need) {
                    s_res[0] = prefix;
                    s_res[1] = idxBase + j;
                }
        }
        __syncthreads();
    }

    const unsigned T    = s_res[0];
    const unsigned idxT = s_res[1];

    // ---- fused noise + mask + dual streaming output, float4 I/O ----
    const float4* dp = reinterpret_cast<const float4*>(data  + base) + (tid << 1);
    const float4* np = reinterpret_cast<const float4*>(noise + base) + (tid << 1);
    float4* mp = reinterpret_cast<float4*>(out_masked + base) + (tid << 1);
    float4* ip = reinterpret_cast<float4*>(out_inv    + base) + (tid << 1);

    #pragma unroll
    for (int h4 = 0; h4 < 2; ++h4) {
        float4 d4 = __ldcs(dp + h4);
        float4 n4 = __ldcs(np + h4);
        float dv[4] = {d4.x, d4.y, d4.z, d4.w};
        float nv[4] = {n4.x, n4.y, n4.z, n4.w};
        float ov[4], gv[4];
        #pragma unroll
        for (int c = 0; c < 4; ++c) {
            int j = h4 * 4 + c;
            bool masked = (r[j] > T) | ((r[j] == T) & (idxBase + j <= idxT));
            ov[c] = masked ? 0.0f : fmaf(0.1f, nv[c], dv[c]);
            gv[c] = masked ? 0.0f : 1.0f;
        }
        __stcs(mp + h4, make_float4(ov[0], ov[1], ov[2], ov[3]));
        __stcs(ip + h4, make_float4(gv[0], gv[1], gv[2], gv[3]));
    }
}

extern "C" void kernel_launch(void* const* d_in, const int* in_sizes, int n_in,
                              void* d_out, int out_size)
{
    const float* data  = (const float*)d_in[0];
    const float* noise = (const float*)d_in[1];
    const float* rv    = (const float*)d_in[2];
    float* out = (float*)d_out;

    size_t n = (size_t)in_sizes[0];   // 32*1024*2048
    int rows = (int)(n / D_DIM);      // 32768

    obs_mask_kernel<<<rows, TPB>>>(data, noise, rv, out, out + n);
}